// round 1
// baseline (speedup 1.0000x reference)
#include <cuda_runtime.h>

// Problem constants (fixed by setup_inputs):
//   FF_AtoB, FF_BtoA: [N=4, K*K=121, H=256, W=256] float32
//   filter_size K = 11, pad = 5. Output: scalar float loss.
#define NB   4
#define HH   256
#define WW   256
#define KK   11
#define PAD  5
#define HW   (HH * WW)           // 65536
#define NPIX (NB * HH * WW)      // 262144

// Scratch (no cudaMalloc allowed): m1 images stored interleaved (x,y) per pixel.
__device__ float2 g_m1A[NPIX];   // filter(grid, FF_AtoB)
__device__ float2 g_m1B[NPIX];   // filter(grid, FF_BtoA)
__device__ float  g_part[512];   // per-block partial sums from pass 2

// Block layout for both passes: blockDim = (64, 2) -> 128 threads.
// threadIdx.x covers the full W in float4 chunks (64 * 4 = 256),
// threadIdx.y covers 2 rows; gridDim.x = NB * HH / 2 = 512 blocks.

__global__ __launch_bounds__(128) void pass1_kernel(
    const float* __restrict__ ffA, const float* __restrict__ ffB)
{
    const int tx = threadIdx.x, ty = threadIdx.y;
    const int b  = blockIdx.x;
    const int n  = b >> 7;                 // 128 blocks per image
    const int h  = ((b & 127) << 1) + ty;
    const int wb = tx << 2;
    const float inv = 1.0f / 255.0f;       // 1/(W-1) == 1/(H-1)

    // Column tables: t = dx + px in [0, 13], ix = wb + t - PAD
    float gxv[14], cf[14];
#pragma unroll
    for (int t = 0; t < 14; ++t) {
        int ix  = wb + t - PAD;
        bool v  = (unsigned)ix < (unsigned)WW;
        gxv[t]  = v ? (float)ix * inv : 0.0f;  // x grid value (0 if out of range)
        cf[t]   = v ? 1.0f : 0.0f;             // column-valid flag
    }

    float m1ax[4] = {0,0,0,0}, m1ay[4] = {0,0,0,0};
    float m1bx[4] = {0,0,0,0}, m1by[4] = {0,0,0,0};

    const size_t base = (size_t)n * (121 * HW) + (size_t)h * WW + wb;

#pragma unroll 1
    for (int dy = 0; dy < KK; ++dy) {
        const int  iy  = h + dy - PAD;
        const bool rv  = (unsigned)iy < (unsigned)HH;
        const float rf  = rv ? 1.0f : 0.0f;
        const float gy0 = rv ? (float)iy * inv : 0.0f;
        const size_t rowbase = base + (size_t)(dy * KK) * HW;
#pragma unroll
        for (int dx = 0; dx < KK; ++dx) {
            const float4 a4 = *reinterpret_cast<const float4*>(ffA + rowbase + (size_t)dx * HW);
            const float4 b4 = *reinterpret_cast<const float4*>(ffB + rowbase + (size_t)dx * HW);
            const float av[4] = {a4.x, a4.y, a4.z, a4.w};
            const float bv[4] = {b4.x, b4.y, b4.z, b4.w};
#pragma unroll
            for (int px = 0; px < 4; ++px) {
                const float xv = gxv[dx + px] * rf;   // grid-x at (iy, ix), zero-padded
                const float yv = cf[dx + px] * gy0;   // grid-y at (iy, ix), zero-padded
                m1ax[px] += av[px] * xv;
                m1ay[px] += av[px] * yv;
                m1bx[px] += bv[px] * xv;
                m1by[px] += bv[px] * yv;
            }
        }
    }

    const size_t o = ((size_t)n * HH + h) * WW + wb;
#pragma unroll
    for (int px = 0; px < 4; ++px) {
        g_m1A[o + px] = make_float2(m1ax[px], m1ay[px]);
        g_m1B[o + px] = make_float2(m1bx[px], m1by[px]);
    }
}

__global__ __launch_bounds__(128) void pass2_kernel(
    const float* __restrict__ ffA, const float* __restrict__ ffB)
{
    const int tx = threadIdx.x, ty = threadIdx.y;
    const int b  = blockIdx.x;
    const int n  = b >> 7;
    const int h  = ((b & 127) << 1) + ty;
    const int wb = tx << 2;
    const float inv = 1.0f / 255.0f;

    // m2_ABA = filter(m1_A, FF_BtoA);  m2_BAB = filter(m1_B, FF_AtoB)
    float m2ax[4] = {0,0,0,0}, m2ay[4] = {0,0,0,0};
    float m2bx[4] = {0,0,0,0}, m2by[4] = {0,0,0,0};

    const size_t base   = (size_t)n * (121 * HW) + (size_t)h * WW + wb;
    const size_t m1base = (size_t)n * HW;

#pragma unroll 1
    for (int dy = 0; dy < KK; ++dy) {
        const int  iy = h + dy - PAD;
        const bool rv = (unsigned)iy < (unsigned)HH;
        const size_t rowbase = base + (size_t)(dy * KK) * HW;
        const size_t m1row   = m1base + (size_t)iy * WW;
#pragma unroll
        for (int dx = 0; dx < KK; ++dx) {
            const float4 a4 = *reinterpret_cast<const float4*>(ffA + rowbase + (size_t)dx * HW);
            const float4 b4 = *reinterpret_cast<const float4*>(ffB + rowbase + (size_t)dx * HW);
            const float av[4] = {a4.x, a4.y, a4.z, a4.w};
            const float bv[4] = {b4.x, b4.y, b4.z, b4.w};
#pragma unroll
            for (int px = 0; px < 4; ++px) {
                const int ix = wb + px + dx - PAD;
                float2 mA = make_float2(0.0f, 0.0f);
                float2 mB = make_float2(0.0f, 0.0f);
                if (rv && (unsigned)ix < (unsigned)WW) {
                    mA = g_m1A[m1row + ix];
                    mB = g_m1B[m1row + ix];
                }
                m2ax[px] += bv[px] * mA.x;
                m2ay[px] += bv[px] * mA.y;
                m2bx[px] += av[px] * mB.x;
                m2by[px] += av[px] * mB.y;
            }
        }
    }

    const float gy = (float)h * inv;
    float acc = 0.0f;
#pragma unroll
    for (int px = 0; px < 4; ++px) {
        const float gx = (float)(wb + px) * inv;
        const float dax = gx - m2ax[px], day = gy - m2ay[px];
        const float dbx = gx - m2bx[px], dby = gy - m2by[px];
        acc += sqrtf(dax * dax + day * day) + sqrtf(dbx * dbx + dby * dby);
    }

    // Deterministic block reduction (128 threads)
    const int ltid = ty * 64 + tx;
#pragma unroll
    for (int off = 16; off > 0; off >>= 1)
        acc += __shfl_down_sync(0xffffffffu, acc, off);
    __shared__ float sred[4];
    if ((ltid & 31) == 0) sred[ltid >> 5] = acc;
    __syncthreads();
    if (ltid == 0)
        g_part[blockIdx.x] = sred[0] + sred[1] + sred[2] + sred[3];
}

__global__ __launch_bounds__(512) void reduce_kernel(float* __restrict__ out)
{
    const int t = threadIdx.x;
    float v = g_part[t];
#pragma unroll
    for (int off = 16; off > 0; off >>= 1)
        v += __shfl_down_sync(0xffffffffu, v, off);
    __shared__ float s[16];
    if ((t & 31) == 0) s[t >> 5] = v;
    __syncthreads();
    if (t == 0) {
        float tot = 0.0f;
#pragma unroll
        for (int i = 0; i < 16; ++i) tot += s[i];
        out[0] = tot * (1.0f / (float)NPIX);   // / (H*W) / N, both directions already summed
    }
}

extern "C" void kernel_launch(void* const* d_in, const int* in_sizes, int n_in,
                              void* d_out, int out_size)
{
    (void)in_sizes; (void)n_in; (void)out_size;
    const float* ffA = (const float*)d_in[0];   // FF_AtoB
    const float* ffB = (const float*)d_in[1];   // FF_BtoA
    float* out = (float*)d_out;

    dim3 blk(64, 2);
    pass1_kernel<<<512, blk>>>(ffA, ffB);
    pass2_kernel<<<512, blk>>>(ffA, ffB);
    reduce_kernel<<<1, 512>>>(out);
}

// round 2
// speedup vs baseline: 1.4615x; 1.4615x over previous
#include <cuda_runtime.h>

// FF_AtoB, FF_BtoA: [N=4, K*K=121, H=256, W=256] float32; K=11, pad=5.
// Output: scalar float loss.
#define NB   4
#define HH   256
#define WW   256
#define KK   11
#define PAD  5
#define HW   (HH * WW)           // 65536
#define NPIX (NB * HH * WW)      // 262144

// m1 scratch packed: (m1A.x, m1A.y, m1B.x, m1B.y) per pixel = 4 MB (fits L2).
__device__ float4 g_m1[NPIX];
__device__ float  g_part[512];

// Both passes: 512 blocks x 256 threads; each block = 2 rows, each thread 2 px.
// tid>>7 selects row within block, (tid&127)*2 = first pixel column.

__global__ __launch_bounds__(256) void pass1_kernel(
    const float* __restrict__ ffA, const float* __restrict__ ffB)
{
    const int tid = threadIdx.x;
    const int b   = blockIdx.x;
    const int n   = b >> 7;
    const int h   = ((b & 127) << 1) + (tid >> 7);
    const int wb  = (tid & 127) << 1;
    const float inv = 1.0f / 255.0f;

    // Column tables: t = dx + px in [0, 12), ix = wb + t - PAD
    float gxv[12], cf[12];
#pragma unroll
    for (int t = 0; t < 12; ++t) {
        int ix = wb + t - PAD;
        bool v = (unsigned)ix < (unsigned)WW;
        gxv[t] = v ? (float)ix * inv : 0.0f;
        cf[t]  = v ? 1.0f : 0.0f;
    }

    float m1ax[2] = {0,0}, m1ay[2] = {0,0};
    float m1bx[2] = {0,0}, m1by[2] = {0,0};

    const size_t base = (size_t)n * (121 * HW) + (size_t)h * WW + wb;

#pragma unroll 1
    for (int dy = 0; dy < KK; ++dy) {
        const int  iy  = h + dy - PAD;
        const bool rv  = (unsigned)iy < (unsigned)HH;
        const float rf  = rv ? 1.0f : 0.0f;
        const float gy0 = rv ? (float)iy * inv : 0.0f;
        const size_t rowbase = base + (size_t)(dy * KK) * HW;
#pragma unroll
        for (int dx = 0; dx < KK; ++dx) {
            const float2 a2 = *reinterpret_cast<const float2*>(ffA + rowbase + (size_t)dx * HW);
            const float2 b2 = *reinterpret_cast<const float2*>(ffB + rowbase + (size_t)dx * HW);
            const float av[2] = {a2.x, a2.y};
            const float bv[2] = {b2.x, b2.y};
#pragma unroll
            for (int px = 0; px < 2; ++px) {
                const float xv = gxv[dx + px] * rf;
                const float yv = cf[dx + px] * gy0;
                m1ax[px] += av[px] * xv;
                m1ay[px] += av[px] * yv;
                m1bx[px] += bv[px] * xv;
                m1by[px] += bv[px] * yv;
            }
        }
    }

    const size_t o = ((size_t)n * HH + h) * WW + wb;
#pragma unroll
    for (int px = 0; px < 2; ++px)
        g_m1[o + px] = make_float4(m1ax[px], m1ay[px], m1bx[px], m1by[px]);
}

__global__ __launch_bounds__(256) void pass2_kernel(
    const float* __restrict__ ffA, const float* __restrict__ ffB)
{
    const int tid = threadIdx.x;
    const int b   = blockIdx.x;
    const int n   = b >> 7;
    const int h   = ((b & 127) << 1) + (tid >> 7);
    const int wb  = (tid & 127) << 1;
    const float inv = 1.0f / 255.0f;

    // m2_ABA = filter(m1_A, FF_BtoA);  m2_BAB = filter(m1_B, FF_AtoB)
    float m2ax[2] = {0,0}, m2ay[2] = {0,0};
    float m2bx[2] = {0,0}, m2by[2] = {0,0};

    const size_t base   = (size_t)n * (121 * HW) + (size_t)h * WW + wb;
    const int    m1base = n * HW;

#pragma unroll 1
    for (int dy = 0; dy < KK; ++dy) {
        const int  iy = h + dy - PAD;
        const bool rv = (unsigned)iy < (unsigned)HH;
        const int  m1row = m1base + iy * WW;

        // Sliding window of m1 for this input row: ix = wb - PAD + t, t in [0,12)
        float4 w[12];
#pragma unroll
        for (int t = 0; t < 12; ++t) {
            const int ix = wb - PAD + t;
            if (rv && (unsigned)ix < (unsigned)WW)
                w[t] = g_m1[m1row + ix];
            else
                w[t] = make_float4(0.0f, 0.0f, 0.0f, 0.0f);
        }

        const size_t rowbase = base + (size_t)(dy * KK) * HW;
#pragma unroll
        for (int dx = 0; dx < KK; ++dx) {
            const float2 a2 = *reinterpret_cast<const float2*>(ffA + rowbase + (size_t)dx * HW);
            const float2 b2 = *reinterpret_cast<const float2*>(ffB + rowbase + (size_t)dx * HW);
            const float av[2] = {a2.x, a2.y};
            const float bv[2] = {b2.x, b2.y};
#pragma unroll
            for (int px = 0; px < 2; ++px) {
                const float4 m = w[dx + px];
                m2ax[px] += bv[px] * m.x;
                m2ay[px] += bv[px] * m.y;
                m2bx[px] += av[px] * m.z;
                m2by[px] += av[px] * m.w;
            }
        }
    }

    const float gy = (float)h * inv;
    float acc = 0.0f;
#pragma unroll
    for (int px = 0; px < 2; ++px) {
        const float gx = (float)(wb + px) * inv;
        const float dax = gx - m2ax[px], day = gy - m2ay[px];
        const float dbx = gx - m2bx[px], dby = gy - m2by[px];
        acc += sqrtf(dax * dax + day * day) + sqrtf(dbx * dbx + dby * dby);
    }

    // Deterministic block reduction (256 threads)
#pragma unroll
    for (int off = 16; off > 0; off >>= 1)
        acc += __shfl_down_sync(0xffffffffu, acc, off);
    __shared__ float sred[8];
    if ((tid & 31) == 0) sred[tid >> 5] = acc;
    __syncthreads();
    if (tid == 0) {
        float t = 0.0f;
#pragma unroll
        for (int i = 0; i < 8; ++i) t += sred[i];
        g_part[blockIdx.x] = t;
    }
}

__global__ __launch_bounds__(512) void reduce_kernel(float* __restrict__ out)
{
    const int t = threadIdx.x;
    float v = g_part[t];
#pragma unroll
    for (int off = 16; off > 0; off >>= 1)
        v += __shfl_down_sync(0xffffffffu, v, off);
    __shared__ float s[16];
    if ((t & 31) == 0) s[t >> 5] = v;
    __syncthreads();
    if (t == 0) {
        float tot = 0.0f;
#pragma unroll
        for (int i = 0; i < 16; ++i) tot += s[i];
        out[0] = tot * (1.0f / (float)NPIX);
    }
}

extern "C" void kernel_launch(void* const* d_in, const int* in_sizes, int n_in,
                              void* d_out, int out_size)
{
    (void)in_sizes; (void)n_in; (void)out_size;
    const float* ffA = (const float*)d_in[0];
    const float* ffB = (const float*)d_in[1];
    float* out = (float*)d_out;

    pass1_kernel<<<512, 256>>>(ffA, ffB);
    pass2_kernel<<<512, 256>>>(ffA, ffB);
    reduce_kernel<<<1, 512>>>(out);
}

// round 3
// speedup vs baseline: 1.4924x; 1.0212x over previous
#include <cuda_runtime.h>

// FF_AtoB, FF_BtoA: [N=4, K*K=121, H=256, W=256] float32; K=11, pad=5.
// Output: scalar float loss.
#define NB   4
#define HH   256
#define WW   256
#define KK   11
#define PAD  5
#define HW   (HH * WW)           // 65536
#define NPIX (NB * HH * WW)      // 262144
#define SW   268                 // smem tile row width in float4 (cols ix=-5..260 -> 266, pad to 268)
#define SM_BYTES (12 * SW * 16)  // 51456

// m1 scratch packed: (m1A.x, m1A.y, m1B.x, m1B.y) per pixel = 4 MB (L2-resident).
__device__ float4 g_m1[NPIX];
__device__ float  g_part[512];

__global__ __launch_bounds__(256) void pass1_kernel(
    const float* __restrict__ ffA, const float* __restrict__ ffB)
{
    const int tid = threadIdx.x;
    const int b   = blockIdx.x;
    const int n   = b >> 7;
    const int h   = ((b & 127) << 1) + (tid >> 7);
    const int wb  = (tid & 127) << 1;
    const float inv = 1.0f / 255.0f;

    float gxv[12], cf[12];
#pragma unroll
    for (int t = 0; t < 12; ++t) {
        int ix = wb + t - PAD;
        bool v = (unsigned)ix < (unsigned)WW;
        gxv[t] = v ? (float)ix * inv : 0.0f;
        cf[t]  = v ? 1.0f : 0.0f;
    }

    float m1ax[2] = {0,0}, m1ay[2] = {0,0};
    float m1bx[2] = {0,0}, m1by[2] = {0,0};

    const size_t base = (size_t)n * (121 * HW) + (size_t)h * WW + wb;

#pragma unroll 1
    for (int dy = 0; dy < KK; ++dy) {
        const int  iy  = h + dy - PAD;
        const bool rv  = (unsigned)iy < (unsigned)HH;
        const float rf  = rv ? 1.0f : 0.0f;
        const float gy0 = rv ? (float)iy * inv : 0.0f;
        const size_t rowbase = base + (size_t)(dy * KK) * HW;
#pragma unroll
        for (int dx = 0; dx < KK; ++dx) {
            const float2 a2 = *reinterpret_cast<const float2*>(ffA + rowbase + (size_t)dx * HW);
            const float2 b2 = *reinterpret_cast<const float2*>(ffB + rowbase + (size_t)dx * HW);
            const float av[2] = {a2.x, a2.y};
            const float bv[2] = {b2.x, b2.y};
#pragma unroll
            for (int px = 0; px < 2; ++px) {
                const float xv = gxv[dx + px] * rf;
                const float yv = cf[dx + px] * gy0;
                m1ax[px] += av[px] * xv;
                m1ay[px] += av[px] * yv;
                m1bx[px] += bv[px] * xv;
                m1by[px] += bv[px] * yv;
            }
        }
    }

    const size_t o = ((size_t)n * HH + h) * WW + wb;
#pragma unroll
    for (int px = 0; px < 2; ++px)
        g_m1[o + px] = make_float4(m1ax[px], m1ay[px], m1bx[px], m1by[px]);
}

__global__ __launch_bounds__(256) void pass2_kernel(
    const float* __restrict__ ffA, const float* __restrict__ ffB)
{
    extern __shared__ float4 sm[];   // [12][SW], logical col ix stored at ix+PAD

    const int tid = threadIdx.x;
    const int b   = blockIdx.x;
    const int n   = b >> 7;
    const int h0  = (b & 127) << 1;
    const float inv = 1.0f / 255.0f;

    // Cooperative fill of m1 halo tile: rows iy = h0-5 .. h0+6, cols ix = -5 .. 262
    const int m1base = n * HW;
#pragma unroll 1
    for (int idx = tid; idx < 12 * SW; idx += 256) {
        const int r  = idx / SW;
        const int s  = idx - r * SW;
        const int iy = h0 - PAD + r;
        const int ix = s - PAD;
        float4 v = make_float4(0.0f, 0.0f, 0.0f, 0.0f);
        if ((unsigned)iy < (unsigned)HH && (unsigned)ix < (unsigned)WW)
            v = g_m1[m1base + iy * WW + ix];
        sm[idx] = v;
    }
    __syncthreads();

    const int ty = tid >> 7;
    const int h  = h0 + ty;
    const int wb = (tid & 127) << 1;

    // m2_ABA = filter(m1_A, FF_BtoA);  m2_BAB = filter(m1_B, FF_AtoB)
    float m2ax[2] = {0,0}, m2ay[2] = {0,0};
    float m2bx[2] = {0,0}, m2by[2] = {0,0};

    const size_t base = (size_t)n * (121 * HW) + (size_t)h * WW + wb;

#pragma unroll 1
    for (int dy = 0; dy < KK; ++dy) {
        // Window for this tap row, straight from smem (no bounds checks).
        const float4* smrow = sm + (ty + dy) * SW + wb;
        float4 w[12];
#pragma unroll
        for (int t = 0; t < 12; ++t) w[t] = smrow[t];

        const size_t rowbase = base + (size_t)(dy * KK) * HW;
#pragma unroll
        for (int dx = 0; dx < KK; ++dx) {
            const float2 a2 = *reinterpret_cast<const float2*>(ffA + rowbase + (size_t)dx * HW);
            const float2 b2 = *reinterpret_cast<const float2*>(ffB + rowbase + (size_t)dx * HW);
            const float av[2] = {a2.x, a2.y};
            const float bv[2] = {b2.x, b2.y};
#pragma unroll
            for (int px = 0; px < 2; ++px) {
                const float4 m = w[dx + px];
                m2ax[px] += bv[px] * m.x;
                m2ay[px] += bv[px] * m.y;
                m2bx[px] += av[px] * m.z;
                m2by[px] += av[px] * m.w;
            }
        }
    }

    const float gy = (float)h * inv;
    float acc = 0.0f;
#pragma unroll
    for (int px = 0; px < 2; ++px) {
        const float gx = (float)(wb + px) * inv;
        const float dax = gx - m2ax[px], day = gy - m2ay[px];
        const float dbx = gx - m2bx[px], dby = gy - m2by[px];
        acc += sqrtf(dax * dax + day * day) + sqrtf(dbx * dbx + dby * dby);
    }

#pragma unroll
    for (int off = 16; off > 0; off >>= 1)
        acc += __shfl_down_sync(0xffffffffu, acc, off);
    __shared__ float sred[8];
    if ((tid & 31) == 0) sred[tid >> 5] = acc;
    __syncthreads();
    if (tid == 0) {
        float t = 0.0f;
#pragma unroll
        for (int i = 0; i < 8; ++i) t += sred[i];
        g_part[blockIdx.x] = t;
    }
}

__global__ __launch_bounds__(512) void reduce_kernel(float* __restrict__ out)
{
    const int t = threadIdx.x;
    float v = g_part[t];
#pragma unroll
    for (int off = 16; off > 0; off >>= 1)
        v += __shfl_down_sync(0xffffffffu, v, off);
    __shared__ float s[16];
    if ((t & 31) == 0) s[t >> 5] = v;
    __syncthreads();
    if (t == 0) {
        float tot = 0.0f;
#pragma unroll
        for (int i = 0; i < 16; ++i) tot += s[i];
        out[0] = tot * (1.0f / (float)NPIX);
    }
}

extern "C" void kernel_launch(void* const* d_in, const int* in_sizes, int n_in,
                              void* d_out, int out_size)
{
    (void)in_sizes; (void)n_in; (void)out_size;
    const float* ffA = (const float*)d_in[0];
    const float* ffB = (const float*)d_in[1];
    float* out = (float*)d_out;

    cudaFuncSetAttribute(pass2_kernel,
                         cudaFuncAttributeMaxDynamicSharedMemorySize, SM_BYTES);

    pass1_kernel<<<512, 256>>>(ffA, ffB);
    pass2_kernel<<<512, 256, SM_BYTES>>>(ffA, ffB);
    reduce_kernel<<<1, 512>>>(out);
}